// round 1
// baseline (speedup 1.0000x reference)
#include <cuda_runtime.h>
#include <math.h>

#define HW     65536      // 256*256
#define NB     8          // batch
#define CF_    64         // feat channels
#define HID_   512
#define KK     64         // mask channels
#define NPIXB  256        // pixels per block (== threads)

// ---------------- scratch (no cudaMalloc allowed) ----------------
__device__ float g_mask[(size_t)NB * KK * HW];   // 134 MB, (b,k,p)
__device__ float g_wc[NB * 3 * KK];              // weighted_color /HW, (b,c,k)
__device__ float g_bkmean[NB * KK];
__device__ float g_bkmax[NB * KK];

// ---------------------------------------------------------------
// K1: fused per-pixel  h = relu(feat@W1 + b1); logits = h@W2 + b2;
//     mask = softmax(logits)  -> g_mask
// thread = pixel. feat vec (64) and logits acc (64) in registers.
// W1/W2 staged in smem in 64-wide HID chunks.
// ---------------------------------------------------------------
__global__ __launch_bounds__(NPIXB, 1)
void k_mask(const float* __restrict__ feat,
            const float* __restrict__ w1, const float* __restrict__ b1,
            const float* __restrict__ w2, const float* __restrict__ b2)
{
    __shared__ float w1s[CF_ * 64];   // [c][dj]  16 KB
    __shared__ float w2s[64 * KK];    // [dj][k]  16 KB
    __shared__ float b1s[HID_];       // 2 KB

    const int b = blockIdx.x >> 8;                       // 256 blocks / batch
    const int p = ((blockIdx.x & 255) << 8) + threadIdx.x;

    for (int i = threadIdx.x; i < HID_; i += NPIXB) b1s[i] = b1[i];

    // load feat vector (coalesced per channel)
    const float* fb = feat + (size_t)b * CF_ * HW + p;
    float f[CF_];
#pragma unroll
    for (int c = 0; c < CF_; c++) f[c] = fb[(size_t)c * HW];

    float acc[KK];
#pragma unroll
    for (int k = 0; k < KK; k++) acc[k] = __ldg(&b2[k]);

    for (int d0 = 0; d0 < HID_; d0 += 64) {
        __syncthreads();
        // stage W1[:, d0:d0+64]  (row c contiguous 64 floats)
        for (int i = threadIdx.x; i < CF_ * 64; i += NPIXB) {
            int c = i >> 6, dj = i & 63;
            w1s[i] = w1[c * HID_ + d0 + dj];
        }
        // stage W2[d0:d0+64, :]  (contiguous block)
        for (int i = threadIdx.x; i < 64 * KK; i += NPIXB)
            w2s[i] = w2[d0 * KK + i];
        __syncthreads();

#pragma unroll 1
        for (int dd = 0; dd < 64; dd += 8) {
            float hv[8];
#pragma unroll
            for (int j = 0; j < 8; j++) hv[j] = b1s[d0 + dd + j];
            // hv[j] += sum_c f[c] * W1[c][dd+j]
#pragma unroll
            for (int c = 0; c < CF_; c++) {
                const float fv = f[c];
                const float4* wp = reinterpret_cast<const float4*>(&w1s[c * 64 + dd]);
                float4 wa = wp[0], wb = wp[1];
                hv[0] = fmaf(fv, wa.x, hv[0]); hv[1] = fmaf(fv, wa.y, hv[1]);
                hv[2] = fmaf(fv, wa.z, hv[2]); hv[3] = fmaf(fv, wa.w, hv[3]);
                hv[4] = fmaf(fv, wb.x, hv[4]); hv[5] = fmaf(fv, wb.y, hv[5]);
                hv[6] = fmaf(fv, wb.z, hv[6]); hv[7] = fmaf(fv, wb.w, hv[7]);
            }
            // acc[k] += relu(hv[j]) * W2[dd+j][k]
#pragma unroll
            for (int j = 0; j < 8; j++) {
                const float h = fmaxf(hv[j], 0.0f);
                const float4* wr = reinterpret_cast<const float4*>(&w2s[(dd + j) * KK]);
#pragma unroll
                for (int k4 = 0; k4 < KK / 4; k4++) {
                    float4 w = wr[k4];
                    acc[k4 * 4 + 0] = fmaf(h, w.x, acc[k4 * 4 + 0]);
                    acc[k4 * 4 + 1] = fmaf(h, w.y, acc[k4 * 4 + 1]);
                    acc[k4 * 4 + 2] = fmaf(h, w.z, acc[k4 * 4 + 2]);
                    acc[k4 * 4 + 3] = fmaf(h, w.w, acc[k4 * 4 + 3]);
                }
            }
        }
    }

    // softmax over K
    float m = acc[0];
#pragma unroll
    for (int k = 1; k < KK; k++) m = fmaxf(m, acc[k]);
    float s = 0.0f;
#pragma unroll
    for (int k = 0; k < KK; k++) { float e = __expf(acc[k] - m); acc[k] = e; s += e; }
    const float inv = 1.0f / s;

    float* gm = g_mask + (size_t)b * KK * HW + p;
#pragma unroll
    for (int k = 0; k < KK; k++) gm[(size_t)k * HW] = acc[k] * inv;
}

// ---------------------------------------------------------------
// K2: per-(b,k) reductions over pixels: sum, max, img-weighted sums
// one block per (b,k). Deterministic (fixed reduction order).
// ---------------------------------------------------------------
__global__ __launch_bounds__(256)
void k_reduce(const float* __restrict__ img)
{
    __shared__ float sm[256];
    const int bk = blockIdx.x;
    const int b = bk >> 6, k = bk & 63;
    const float* gm = g_mask + (size_t)bk * HW;
    const float* im = img + (size_t)b * 3 * HW;

    float s = 0.f, mx = -1e30f, c0 = 0.f, c1 = 0.f, c2 = 0.f;
    for (int p = threadIdx.x; p < HW; p += 256) {
        const float mv = gm[p];
        s += mv;
        mx = fmaxf(mx, mv);
        c0 = fmaf(mv, im[p],            c0);
        c1 = fmaf(mv, im[p + HW],       c1);
        c2 = fmaf(mv, im[p + 2 * HW],   c2);
    }

    const int t = threadIdx.x;
    float ts, tc0, tc1, tc2, tmx;
    // sums
    sm[t] = s;  __syncthreads();
    for (int st = 128; st > 0; st >>= 1) { if (t < st) sm[t] += sm[t + st]; __syncthreads(); }
    ts = sm[0]; __syncthreads();
    sm[t] = c0; __syncthreads();
    for (int st = 128; st > 0; st >>= 1) { if (t < st) sm[t] += sm[t + st]; __syncthreads(); }
    tc0 = sm[0]; __syncthreads();
    sm[t] = c1; __syncthreads();
    for (int st = 128; st > 0; st >>= 1) { if (t < st) sm[t] += sm[t + st]; __syncthreads(); }
    tc1 = sm[0]; __syncthreads();
    sm[t] = c2; __syncthreads();
    for (int st = 128; st > 0; st >>= 1) { if (t < st) sm[t] += sm[t + st]; __syncthreads(); }
    tc2 = sm[0]; __syncthreads();
    // max
    sm[t] = mx; __syncthreads();
    for (int st = 128; st > 0; st >>= 1) { if (t < st) sm[t] = fmaxf(sm[t], sm[t + st]); __syncthreads(); }
    tmx = sm[0];

    if (t == 0) {
        const float invhw = 1.0f / (float)HW;
        g_bkmean[bk] = ts * invhw;
        g_bkmax[bk]  = tmx;
        g_wc[(b * 3 + 0) * KK + k] = tc0 * invhw;
        g_wc[(b * 3 + 1) * KK + k] = tc1 * invhw;
        g_wc[(b * 3 + 2) * KK + k] = tc2 * invhw;
    }
}

// ---------------------------------------------------------------
// K3: scalar outputs. out[N] = mean_max, out[N+1] = std_mean
// ---------------------------------------------------------------
__global__ void k_final(float* __restrict__ out)
{
    __shared__ float sm[512];
    __shared__ float bmean[NB], bstd[NB];
    const int t = threadIdx.x;

    // mean of per-(b,k) maxima
    sm[t] = g_bkmax[t]; __syncthreads();
    for (int st = 256; st > 0; st >>= 1) { if (t < st) sm[t] += sm[t + st]; __syncthreads(); }
    if (t == 0) out[(size_t)NB * 3 * HW] = sm[0] * (1.0f / 512.0f);
    __syncthreads();

    // std over k (ddof=1) of per-(b,k) means, then mean over b
    const float mv = g_bkmean[t];
    sm[t] = mv; __syncthreads();
    if (t < NB) {
        float sb = 0.f;
        for (int k = 0; k < KK; k++) sb += sm[t * KK + k];
        bmean[t] = sb * (1.0f / KK);
    }
    __syncthreads();
    const float d = mv - bmean[t >> 6];
    sm[t] = d * d; __syncthreads();
    if (t < NB) {
        float sb = 0.f;
        for (int k = 0; k < KK; k++) sb += sm[t * KK + k];
        bstd[t] = sqrtf(sb / (float)(KK - 1));
    }
    __syncthreads();
    if (t == 0) {
        float sb = 0.f;
        for (int b = 0; b < NB; b++) sb += bstd[b];
        out[(size_t)NB * 3 * HW + 1] = sb * (1.0f / NB);
    }
}

// ---------------------------------------------------------------
// K4: transformed_img[b,c,p] = sum_k mask[b,k,p] * wc[b,c,k]
// ---------------------------------------------------------------
__global__ __launch_bounds__(256)
void k_transform(float* __restrict__ out)
{
    __shared__ float wcs[3 * KK];
    const int b = blockIdx.x >> 8;
    const int p = ((blockIdx.x & 255) << 8) + threadIdx.x;
    if (threadIdx.x < 3 * KK) wcs[threadIdx.x] = g_wc[b * 3 * KK + threadIdx.x];
    __syncthreads();

    const float* gm = g_mask + (size_t)b * KK * HW + p;
    float o0 = 0.f, o1 = 0.f, o2 = 0.f;
#pragma unroll
    for (int k = 0; k < KK; k++) {
        const float mv = gm[(size_t)k * HW];
        o0 = fmaf(mv, wcs[k],          o0);
        o1 = fmaf(mv, wcs[KK + k],     o1);
        o2 = fmaf(mv, wcs[2 * KK + k], o2);
    }
    out[((size_t)b * 3 + 0) * HW + p] = o0;
    out[((size_t)b * 3 + 1) * HW + p] = o1;
    out[((size_t)b * 3 + 2) * HW + p] = o2;
}

// ---------------------------------------------------------------
extern "C" void kernel_launch(void* const* d_in, const int* in_sizes, int n_in,
                              void* d_out, int out_size)
{
    const float* img  = (const float*)d_in[0];
    const float* feat = (const float*)d_in[1];
    // d_in[2] = coord_map (unused by reference)
    const float* w1 = (const float*)d_in[3];
    const float* b1 = (const float*)d_in[4];
    const float* w2 = (const float*)d_in[5];
    const float* b2 = (const float*)d_in[6];
    float* out = (float*)d_out;

    k_mask<<<NB * (HW / NPIXB), NPIXB>>>(feat, w1, b1, w2, b2);
    k_reduce<<<NB * KK, 256>>>(img);
    k_final<<<1, 512>>>(out);
    k_transform<<<NB * (HW / NPIXB), NPIXB>>>(out);
}

// round 2
// speedup vs baseline: 3.2144x; 3.2144x over previous
#include <cuda_runtime.h>
#include <cuda_fp16.h>
#include <math.h>

#define HW     65536      // 256*256
#define NB     8
#define CF_    64
#define HID_   512
#define KK     64
#define TP     128        // pixels per block
#define NTHREADS 256

// ---------------- scratch ----------------
__device__ float g_mask[(size_t)NB * KK * HW];   // (b,k,p)
__device__ float g_wc[NB * 3 * KK];
__device__ float g_bkmean[NB * KK];
__device__ float g_bkmax[NB * KK];

// ---------------- dynamic smem layout (bytes) ----------------
#define XS_PITCH 132                       // floats; conflict-free for frag reads & mask stage
#define W1_PITCH 136                       // half2 units
#define W2_PITCH 72                        // half2 units
#define XS_OFF   0                         // 64 x 132 floats = 33792 B  (union: X tile / mask tile)
#define W1HI_OFF (33792)
#define W1LO_OFF (W1HI_OFF + 32*W1_PITCH*4)
#define W2HI_OFF (W1LO_OFF + 32*W1_PITCH*4)
#define W2LO_OFF (W2HI_OFF + 64*W2_PITCH*4)
#define B1_OFF   (W2LO_OFF + 64*W2_PITCH*4)
#define B2_OFF   (B1_OFF + 512*4)
#define SMEM_TOTAL (B2_OFF + 64*4)         // = 107,776 B

// ---------------------------------------------------------------
__device__ __forceinline__ void mma16816(float c[4], const unsigned a[4],
                                         unsigned b0, unsigned b1)
{
    asm volatile(
        "mma.sync.aligned.m16n8k16.row.col.f32.f16.f16.f32 "
        "{%0,%1,%2,%3},{%4,%5,%6,%7},{%8,%9},{%0,%1,%2,%3};\n"
        : "+f"(c[0]), "+f"(c[1]), "+f"(c[2]), "+f"(c[3])
        : "r"(a[0]), "r"(a[1]), "r"(a[2]), "r"(a[3]), "r"(b0), "r"(b1));
}

// split (x,y) into hi half2 + residual-lo half2
__device__ __forceinline__ void split2(float x, float y, unsigned &hi, unsigned &lo)
{
    __half hx = __float2half_rn(x);
    __half hy = __float2half_rn(y);
    __half lx = __float2half_rn(x - __half2float(hx));
    __half ly = __float2half_rn(y - __half2float(hy));
    __half2 h2 = __halves2half2(hx, hy);
    __half2 l2 = __halves2half2(lx, ly);
    hi = *reinterpret_cast<unsigned*>(&h2);
    lo = *reinterpret_cast<unsigned*>(&l2);
}

// ---------------------------------------------------------------
// K1: fused GEMM1(relu) + GEMM2 + softmax via fp16 split-3 tensor-core MMA
// block = 128 pixels, 8 warps, each warp = 16 pixels (one m16 tile), full K=64.
// ---------------------------------------------------------------
__global__ __launch_bounds__(NTHREADS)
void k_mask(const float* __restrict__ feat,
            const float* __restrict__ w1, const float* __restrict__ b1,
            const float* __restrict__ w2, const float* __restrict__ b2)
{
    extern __shared__ char smem[];
    float*    xs   = (float*)(smem + XS_OFF);       // [64][132] X tile, later mask tile
    unsigned* w1hi = (unsigned*)(smem + W1HI_OFF);  // [32 cpair][136] half2
    unsigned* w1lo = (unsigned*)(smem + W1LO_OFF);
    unsigned* w2hi = (unsigned*)(smem + W2HI_OFF);  // [64 hidpair][72] half2
    unsigned* w2lo = (unsigned*)(smem + W2LO_OFF);
    float*    b1s  = (float*)(smem + B1_OFF);
    float*    b2s  = (float*)(smem + B2_OFF);

    const int tid  = threadIdx.x;
    const int warp = tid >> 5;
    const int lane = tid & 31;
    const int q    = lane & 3;       // k-pair / col group
    const int g    = lane >> 2;      // row group 0..7
    const int nl   = lane >> 2;      // B-frag n index 0..7

    const int b  = blockIdx.x >> 9;            // 512 blocks per batch
    const int p0 = (blockIdx.x & 511) * TP;

    for (int i = tid; i < HID_; i += NTHREADS) b1s[i] = b1[i];
    if (tid < KK) b2s[tid] = b2[tid];

    // stage X tile: 64 channels x 128 pixels (coalesced per channel)
    {
        const float* fb = feat + (size_t)b * CF_ * HW + p0;
        for (int i = tid; i < CF_ * TP; i += NTHREADS) {
            int c = i >> 7, px = i & 127;
            xs[c * XS_PITCH + px] = fb[(size_t)c * HW + px];
        }
    }
    __syncthreads();

    // build A fragments (hi/lo) for 4 channel-chunks of 16
    const int prow = warp * 16 + g;     // local pixel row for a0/a2; +8 for a1/a3
    unsigned xa_hi[4][4], xa_lo[4][4];
#pragma unroll
    for (int cc = 0; cc < 4; cc++) {
#pragma unroll
        for (int hlf = 0; hlf < 2; hlf++) {           // k 0..7 vs 8..15
            int c0i = cc * 16 + hlf * 8 + 2 * q;
            float x0 = xs[c0i * XS_PITCH + prow];
            float x1 = xs[(c0i + 1) * XS_PITCH + prow];
            float x2 = xs[c0i * XS_PITCH + prow + 8];
            float x3 = xs[(c0i + 1) * XS_PITCH + prow + 8];
            split2(x0, x1, xa_hi[cc][hlf * 2 + 0], xa_lo[cc][hlf * 2 + 0]);
            split2(x2, x3, xa_hi[cc][hlf * 2 + 1], xa_lo[cc][hlf * 2 + 1]);
        }
    }

    // logits accumulators, init with b2
    float acc[8][4];
#pragma unroll
    for (int kn = 0; kn < 8; kn++) {
        float bb0 = b2s[kn * 8 + 2 * q], bb1 = b2s[kn * 8 + 2 * q + 1];
        acc[kn][0] = bb0; acc[kn][1] = bb1; acc[kn][2] = bb0; acc[kn][3] = bb1;
    }

    // ---- hid superchunks of 128 ----
    for (int d0 = 0; d0 < HID_; d0 += 128) {
        __syncthreads();
        // stage W1 chunk as pre-split half2 pairs along c: [32 cpair][128 hid]
        for (int i = tid; i < 32 * 128; i += NTHREADS) {
            int cp = i >> 7, j = i & 127;
            float a  = w1[(2 * cp) * HID_ + d0 + j];
            float bv = w1[(2 * cp + 1) * HID_ + d0 + j];
            unsigned hi, lo; split2(a, bv, hi, lo);
            w1hi[cp * W1_PITCH + j] = hi;
            w1lo[cp * W1_PITCH + j] = lo;
        }
        // stage W2 chunk: pairs along hid: [64 hidpair][64 k]
        for (int i = tid; i < 64 * 64; i += NTHREADS) {
            int hp = i >> 6, k = i & 63;
            float a  = w2[(size_t)(d0 + 2 * hp) * KK + k];
            float bv = w2[(size_t)(d0 + 2 * hp + 1) * KK + k];
            unsigned hi, lo; split2(a, bv, hi, lo);
            w2hi[hp * W2_PITCH + k] = hi;
            w2lo[hp * W2_PITCH + k] = lo;
        }
        __syncthreads();

#pragma unroll 1
        for (int hc = 0; hc < 8; hc++) {            // 8 hid-16 chunks
            const int h0 = d0 + hc * 16;
            // ---- GEMM1: z[0] = cols h0..h0+7, z[1] = cols h0+8..h0+15 ----
            float z[2][4];
#pragma unroll
            for (int nc = 0; nc < 2; nc++) {
                float bb0 = b1s[h0 + nc * 8 + 2 * q];
                float bb1 = b1s[h0 + nc * 8 + 2 * q + 1];
                z[nc][0] = bb0; z[nc][1] = bb1; z[nc][2] = bb0; z[nc][3] = bb1;
            }
#pragma unroll
            for (int cc = 0; cc < 4; cc++) {
#pragma unroll
                for (int nc = 0; nc < 2; nc++) {
                    int col = hc * 16 + nc * 8 + nl;
                    unsigned b0h = w1hi[(cc * 8 + q) * W1_PITCH + col];
                    unsigned b1h = w1hi[(cc * 8 + q + 4) * W1_PITCH + col];
                    unsigned b0l = w1lo[(cc * 8 + q) * W1_PITCH + col];
                    unsigned b1l = w1lo[(cc * 8 + q + 4) * W1_PITCH + col];
                    mma16816(z[nc], xa_hi[cc], b0h, b1h);
                    mma16816(z[nc], xa_hi[cc], b0l, b1l);
                    mma16816(z[nc], xa_lo[cc], b0h, b1h);
                }
            }
            // ---- ReLU + split + repack C->A (layouts match natively) ----
            unsigned Ah[4], Al[4];
            split2(fmaxf(z[0][0], 0.f), fmaxf(z[0][1], 0.f), Ah[0], Al[0]);
            split2(fmaxf(z[0][2], 0.f), fmaxf(z[0][3], 0.f), Ah[1], Al[1]);
            split2(fmaxf(z[1][0], 0.f), fmaxf(z[1][1], 0.f), Ah[2], Al[2]);
            split2(fmaxf(z[1][2], 0.f), fmaxf(z[1][3], 0.f), Ah[3], Al[3]);
            // ---- GEMM2: accumulate logits ----
#pragma unroll
            for (int kn = 0; kn < 8; kn++) {
                unsigned b0h = w2hi[(hc * 8 + q) * W2_PITCH + kn * 8 + nl];
                unsigned b1h = w2hi[(hc * 8 + q + 4) * W2_PITCH + kn * 8 + nl];
                unsigned b0l = w2lo[(hc * 8 + q) * W2_PITCH + kn * 8 + nl];
                unsigned b1l = w2lo[(hc * 8 + q + 4) * W2_PITCH + kn * 8 + nl];
                mma16816(acc[kn], Ah, b0h, b1h);
                mma16816(acc[kn], Ah, b0l, b1l);
                mma16816(acc[kn], Al, b0h, b1h);
            }
        }
    }

    // ---- softmax over K (rows prow and prow+8) ----
    float mA = -1e30f, mB = -1e30f;
#pragma unroll
    for (int kn = 0; kn < 8; kn++) {
        mA = fmaxf(mA, fmaxf(acc[kn][0], acc[kn][1]));
        mB = fmaxf(mB, fmaxf(acc[kn][2], acc[kn][3]));
    }
    mA = fmaxf(mA, __shfl_xor_sync(0xffffffffu, mA, 1));
    mA = fmaxf(mA, __shfl_xor_sync(0xffffffffu, mA, 2));
    mB = fmaxf(mB, __shfl_xor_sync(0xffffffffu, mB, 1));
    mB = fmaxf(mB, __shfl_xor_sync(0xffffffffu, mB, 2));
    float sA = 0.f, sB = 0.f;
#pragma unroll
    for (int kn = 0; kn < 8; kn++) {
        acc[kn][0] = __expf(acc[kn][0] - mA); sA += acc[kn][0];
        acc[kn][1] = __expf(acc[kn][1] - mA); sA += acc[kn][1];
        acc[kn][2] = __expf(acc[kn][2] - mB); sB += acc[kn][2];
        acc[kn][3] = __expf(acc[kn][3] - mB); sB += acc[kn][3];
    }
    sA += __shfl_xor_sync(0xffffffffu, sA, 1);
    sA += __shfl_xor_sync(0xffffffffu, sA, 2);
    sB += __shfl_xor_sync(0xffffffffu, sB, 1);
    sB += __shfl_xor_sync(0xffffffffu, sB, 2);
    const float invA = 1.0f / sA, invB = 1.0f / sB;

    // stage mask tile into smem (reuse xs region): ms[k][pix], pitch 132
#pragma unroll
    for (int kn = 0; kn < 8; kn++) {
        int c0 = kn * 8 + 2 * q;
        xs[c0 * XS_PITCH + prow]           = acc[kn][0] * invA;
        xs[(c0 + 1) * XS_PITCH + prow]     = acc[kn][1] * invA;
        xs[c0 * XS_PITCH + prow + 8]       = acc[kn][2] * invB;
        xs[(c0 + 1) * XS_PITCH + prow + 8] = acc[kn][3] * invB;
    }
    __syncthreads();

    // coalesced mask store
    float* gm = g_mask + (size_t)b * KK * HW + p0;
    for (int i = tid; i < KK * TP; i += NTHREADS) {
        int k = i >> 7, px = i & 127;
        gm[(size_t)k * HW + px] = xs[k * XS_PITCH + px];
    }
}

// ---------------------------------------------------------------
// K2: per-(b,k) reductions over pixels: sum, max, img-weighted sums
// ---------------------------------------------------------------
__global__ __launch_bounds__(256)
void k_reduce(const float* __restrict__ img)
{
    __shared__ float sm[256];
    const int bk = blockIdx.x;
    const int b = bk >> 6, k = bk & 63;
    const float* gm = g_mask + (size_t)bk * HW;
    const float* im = img + (size_t)b * 3 * HW;

    float s = 0.f, mx = -1e30f, c0 = 0.f, c1 = 0.f, c2 = 0.f;
    for (int p = threadIdx.x; p < HW; p += 256) {
        const float mv = gm[p];
        s += mv;
        mx = fmaxf(mx, mv);
        c0 = fmaf(mv, im[p],          c0);
        c1 = fmaf(mv, im[p + HW],     c1);
        c2 = fmaf(mv, im[p + 2 * HW], c2);
    }

    const int t = threadIdx.x;
    float ts, tc0, tc1, tc2, tmx;
    sm[t] = s;  __syncthreads();
    for (int st = 128; st > 0; st >>= 1) { if (t < st) sm[t] += sm[t + st]; __syncthreads(); }
    ts = sm[0]; __syncthreads();
    sm[t] = c0; __syncthreads();
    for (int st = 128; st > 0; st >>= 1) { if (t < st) sm[t] += sm[t + st]; __syncthreads(); }
    tc0 = sm[0]; __syncthreads();
    sm[t] = c1; __syncthreads();
    for (int st = 128; st > 0; st >>= 1) { if (t < st) sm[t] += sm[t + st]; __syncthreads(); }
    tc1 = sm[0]; __syncthreads();
    sm[t] = c2; __syncthreads();
    for (int st = 128; st > 0; st >>= 1) { if (t < st) sm[t] += sm[t + st]; __syncthreads(); }
    tc2 = sm[0]; __syncthreads();
    sm[t] = mx; __syncthreads();
    for (int st = 128; st > 0; st >>= 1) { if (t < st) sm[t] = fmaxf(sm[t], sm[t + st]); __syncthreads(); }
    tmx = sm[0];

    if (t == 0) {
        const float invhw = 1.0f / (float)HW;
        g_bkmean[bk] = ts * invhw;
        g_bkmax[bk]  = tmx;
        g_wc[(b * 3 + 0) * KK + k] = tc0 * invhw;
        g_wc[(b * 3 + 1) * KK + k] = tc1 * invhw;
        g_wc[(b * 3 + 2) * KK + k] = tc2 * invhw;
    }
}

// ---------------------------------------------------------------
// K3: scalar outputs
// ---------------------------------------------------------------
__global__ void k_final(float* __restrict__ out)
{
    __shared__ float sm[512];
    __shared__ float bmean[NB], bstd[NB];
    const int t = threadIdx.x;

    sm[t] = g_bkmax[t]; __syncthreads();
    for (int st = 256; st > 0; st >>= 1) { if (t < st) sm[t] += sm[t + st]; __syncthreads(); }
    if (t == 0) out[(size_t)NB * 3 * HW] = sm[0] * (1.0f / 512.0f);
    __syncthreads();

    const float mv = g_bkmean[t];
    sm[t] = mv; __syncthreads();
    if (t < NB) {
        float sb = 0.f;
        for (int k = 0; k < KK; k++) sb += sm[t * KK + k];
        bmean[t] = sb * (1.0f / KK);
    }
    __syncthreads();
    const float d = mv - bmean[t >> 6];
    sm[t] = d * d; __syncthreads();
    if (t < NB) {
        float sb = 0.f;
        for (int k = 0; k < KK; k++) sb += sm[t * KK + k];
        bstd[t] = sqrtf(sb / (float)(KK - 1));
    }
    __syncthreads();
    if (t == 0) {
        float sb = 0.f;
        for (int b = 0; b < NB; b++) sb += bstd[b];
        out[(size_t)NB * 3 * HW + 1] = sb * (1.0f / NB);
    }
}

// ---------------------------------------------------------------
// K4: transformed_img[b,c,p] = sum_k mask[b,k,p] * wc[b,c,k]
// ---------------------------------------------------------------
__global__ __launch_bounds__(256)
void k_transform(float* __restrict__ out)
{
    __shared__ float wcs[3 * KK];
    const int b = blockIdx.x >> 8;
    const int p = ((blockIdx.x & 255) << 8) + threadIdx.x;
    if (threadIdx.x < 3 * KK) wcs[threadIdx.x] = g_wc[b * 3 * KK + threadIdx.x];
    __syncthreads();

    const float* gm = g_mask + (size_t)b * KK * HW + p;
    float o0 = 0.f, o1 = 0.f, o2 = 0.f;
#pragma unroll
    for (int k = 0; k < KK; k++) {
        const float mv = gm[(size_t)k * HW];
        o0 = fmaf(mv, wcs[k],          o0);
        o1 = fmaf(mv, wcs[KK + k],     o1);
        o2 = fmaf(mv, wcs[2 * KK + k], o2);
    }
    out[((size_t)b * 3 + 0) * HW + p] = o0;
    out[((size_t)b * 3 + 1) * HW + p] = o1;
    out[((size_t)b * 3 + 2) * HW + p] = o2;
}

// ---------------------------------------------------------------
extern "C" void kernel_launch(void* const* d_in, const int* in_sizes, int n_in,
                              void* d_out, int out_size)
{
    const float* img  = (const float*)d_in[0];
    const float* feat = (const float*)d_in[1];
    // d_in[2] = coord_map (unused by reference)
    const float* w1 = (const float*)d_in[3];
    const float* b1 = (const float*)d_in[4];
    const float* w2 = (const float*)d_in[5];
    const float* b2 = (const float*)d_in[6];
    float* out = (float*)d_out;

    cudaFuncSetAttribute(k_mask, cudaFuncAttributeMaxDynamicSharedMemorySize, SMEM_TOTAL);

    k_mask<<<NB * (HW / TP), NTHREADS, SMEM_TOTAL>>>(feat, w1, b1, w2, b2);
    k_reduce<<<NB * KK, 256>>>(img);
    k_final<<<1, 512>>>(out);
    k_transform<<<NB * (HW / 256), 256>>>(out);
}

// round 4
// speedup vs baseline: 3.8544x; 1.1991x over previous
#include <cuda_runtime.h>
#include <cuda_fp16.h>
#include <math.h>

#define HW     65536      // 256*256
#define NB     8
#define CF_    64
#define HID_   512
#define KK     64
#define TP     128        // pixels per CTA
#define NT     128        // threads per CTA (4 warps, each 32 pixels = 2 m16 tiles)

// ---------------- scratch ----------------
__device__ float g_mask[(size_t)NB * KK * HW];   // (b,k,p)
__device__ float g_wc[NB * 3 * KK];
__device__ float g_bkmean[NB * KK];
__device__ float g_bkmax[NB * KK];
// pre-split weights as half2 (unsigned): B-fragment-ready layouts
__device__ __align__(16) unsigned g1hi[32 * 512];   // [cpair][hid]
__device__ __align__(16) unsigned g1lo[32 * 512];
__device__ __align__(16) unsigned g2hi[256 * 64];   // [hidpair][k]
__device__ __align__(16) unsigned g2lo[256 * 64];

// ---------------- smem layout (bytes from dynamic base) ----------------
#define XS_PITCH 132
#define WPITCH   72                       // words; (72 mod 32)=8 -> conflict-free frag reads
#define OFF_XS   0                        // 64 x 132 x 4 = 33792 (feat tile / mask tile)
#define OFF_W1   33792                    // 2 bufs x (hi 9216 + lo 9216) = 36864
#define OFF_W2   (OFF_W1 + 36864)         // 36864
#define OFF_B1   (OFF_W2 + 36864)         // 2048
#define OFF_B2   (OFF_B1 + 2048)          // 256
#define SMEM_REQ (OFF_B2 + 256)           // 109,824 B  -> 2 CTAs/SM

// ---------------- helpers ----------------
__device__ __forceinline__ unsigned smem_u32(const void* p) {
    unsigned a;
    asm("{ .reg .u64 t; cvta.to.shared.u64 t, %1; cvt.u32.u64 %0, t; }" : "=r"(a) : "l"(p));
    return a;
}
#define CP16(dst, src) \
    asm volatile("cp.async.cg.shared.global [%0], [%1], 16;" :: "r"(dst), "l"(src) : "memory")
#define CP_COMMIT() asm volatile("cp.async.commit_group;" ::: "memory")
#define CP_WAIT(n)  asm volatile("cp.async.wait_group %0;" :: "n"(n) : "memory")

__device__ __forceinline__ void mma16816(float c[4], const unsigned a[4],
                                         unsigned b0, unsigned b1)
{
    asm volatile(
        "mma.sync.aligned.m16n8k16.row.col.f32.f16.f16.f32 "
        "{%0,%1,%2,%3},{%4,%5,%6,%7},{%8,%9},{%0,%1,%2,%3};\n"
        : "+f"(c[0]), "+f"(c[1]), "+f"(c[2]), "+f"(c[3])
        : "r"(a[0]), "r"(a[1]), "r"(a[2]), "r"(a[3]), "r"(b0), "r"(b1));
}
__device__ __forceinline__ void split2(float x, float y, unsigned &hi, unsigned &lo)
{
    __half hx = __float2half_rn(x), hy = __float2half_rn(y);
    __half lx = __float2half_rn(x - __half2float(hx));
    __half ly = __float2half_rn(y - __half2float(hy));
    __half2 h2 = __halves2half2(hx, hy), l2 = __halves2half2(lx, ly);
    hi = *reinterpret_cast<unsigned*>(&h2);
    lo = *reinterpret_cast<unsigned*>(&l2);
}

// ---------------------------------------------------------------
// prep: split weights into half2 hi/lo in fragment-ready layouts
// ---------------------------------------------------------------
__global__ void k_prep(const float* __restrict__ w1, const float* __restrict__ w2)
{
    int i = blockIdx.x * blockDim.x + threadIdx.x;
    if (i < 32 * 512) {
        int cp = i >> 9, d = i & 511;
        split2(w1[(2 * cp) * HID_ + d], w1[(2 * cp + 1) * HID_ + d], g1hi[i], g1lo[i]);
    } else if (i < 2 * 32 * 512) {
        int j = i - 32 * 512;
        int hp = j >> 6, k = j & 63;
        split2(w2[(2 * hp) * KK + k], w2[(2 * hp + 1) * KK + k], g2hi[j], g2lo[j]);
    }
}

// stage one 64-hid chunk (w1 hi/lo + w2 hi/lo) via cp.async into buffer `buf`
__device__ __forceinline__ void stage_chunk(unsigned sbase, int c, int buf, int tid)
{
    const unsigned w1d = sbase + OFF_W1 + (unsigned)buf * 18432u;
    const unsigned w2d = sbase + OFF_W2 + (unsigned)buf * 18432u;
#pragma unroll
    for (int i = tid; i < 512; i += NT) {
        int cp = i >> 4, seg = i & 15;
        unsigned doff = (unsigned)(cp * WPITCH + seg * 4) * 4u;
        CP16(w1d + doff,         g1hi + cp * 512 + c * 64 + seg * 4);
        CP16(w1d + 9216 + doff,  g1lo + cp * 512 + c * 64 + seg * 4);
        CP16(w2d + doff,         g2hi + (c * 32 + cp) * 64 + seg * 4);
        CP16(w2d + 9216 + doff,  g2lo + (c * 32 + cp) * 64 + seg * 4);
    }
}

// ---------------------------------------------------------------
// K1: fused GEMM1(relu)+GEMM2+softmax, fp16 split-3 mma.sync
// 128 threads / 128 pixels; warp = 32 pixels (2 m16 tiles, B-frags shared)
// ---------------------------------------------------------------
__global__ __launch_bounds__(NT, 2)
void k_mask(const float* __restrict__ feat,
            const float* __restrict__ b1, const float* __restrict__ b2)
{
    extern __shared__ __align__(16) char sm[];
    const unsigned sbase = smem_u32(sm);
    float* xs  = (float*)(sm + OFF_XS);
    float* b1s = (float*)(sm + OFF_B1);
    float* b2s = (float*)(sm + OFF_B2);

    const int tid  = threadIdx.x;
    const int warp = tid >> 5;
    const int lane = tid & 31;
    const int q    = lane & 3;      // k-quad
    const int g    = lane >> 2;     // row in group / B n-index
    const int nl   = g;

    const int b  = blockIdx.x >> 9;              // 512 blocks per batch
    const int p0 = (blockIdx.x & 511) * TP;

    // kick off weight chunk 0 immediately
    stage_chunk(sbase, 0, 0, tid);
    CP_COMMIT();

    for (int i = tid; i < HID_; i += NT) b1s[i] = b1[i];
    if (tid < KK) b2s[tid] = b2[tid];

    // stage feat tile: 64 ch x 128 px
    {
        const float* fb = feat + (size_t)b * CF_ * HW + p0;
        for (int i = tid; i < CF_ * TP; i += NT) {
            int c = i >> 7, px = i & 127;
            xs[c * XS_PITCH + px] = fb[(size_t)c * HW + px];
        }
    }
    __syncthreads();

    // build A fragments for both tiles (rows: warp*32 + t*16 + g / +8)
    unsigned xah[2][4][4], xal[2][4][4];
#pragma unroll
    for (int t = 0; t < 2; t++) {
        const int prow = warp * 32 + t * 16 + g;
#pragma unroll
        for (int cc = 0; cc < 4; cc++) {
#pragma unroll
            for (int hlf = 0; hlf < 2; hlf++) {
                int c0i = cc * 16 + hlf * 8 + 2 * q;
                float x0 = xs[c0i * XS_PITCH + prow];
                float x1 = xs[(c0i + 1) * XS_PITCH + prow];
                float x2 = xs[c0i * XS_PITCH + prow + 8];
                float x3 = xs[(c0i + 1) * XS_PITCH + prow + 8];
                split2(x0, x1, xah[t][cc][hlf * 2 + 0], xal[t][cc][hlf * 2 + 0]);
                split2(x2, x3, xah[t][cc][hlf * 2 + 1], xal[t][cc][hlf * 2 + 1]);
            }
        }
    }

    // logits accumulators (both tiles), init with b2
    float acc[2][8][4];
#pragma unroll
    for (int kn = 0; kn < 8; kn++) {
        float bb0 = b2s[kn * 8 + 2 * q], bb1 = b2s[kn * 8 + 2 * q + 1];
#pragma unroll
        for (int t = 0; t < 2; t++) {
            acc[t][kn][0] = bb0; acc[t][kn][1] = bb1;
            acc[t][kn][2] = bb0; acc[t][kn][3] = bb1;
        }
    }

    // ---- 8 double-buffered 64-hid chunks ----
    for (int c = 0; c < 8; c++) {
        if (c < 7) { stage_chunk(sbase, c + 1, (c + 1) & 1, tid); CP_COMMIT(); CP_WAIT(1); }
        else       { CP_WAIT(0); }
        __syncthreads();

        const unsigned* w1hi = (const unsigned*)(sm + OFF_W1 + (c & 1) * 18432);
        const unsigned* w1lo = w1hi + 2304;   // 9216 B
        const unsigned* w2hi = (const unsigned*)(sm + OFF_W2 + (c & 1) * 18432);
        const unsigned* w2lo = w2hi + 2304;

#pragma unroll
        for (int hc = 0; hc < 4; hc++) {           // 4 x 16-hid subchunks
            const int h0 = c * 64 + hc * 16;
            float z[2][2][4];
#pragma unroll
            for (int nc = 0; nc < 2; nc++) {
                float bb0 = b1s[h0 + nc * 8 + 2 * q];
                float bb1 = b1s[h0 + nc * 8 + 2 * q + 1];
#pragma unroll
                for (int t = 0; t < 2; t++) {
                    z[t][nc][0] = bb0; z[t][nc][1] = bb1;
                    z[t][nc][2] = bb0; z[t][nc][3] = bb1;
                }
            }
            // GEMM1: B-frags loaded once, used by both tiles
#pragma unroll
            for (int cc = 0; cc < 4; cc++) {
#pragma unroll
                for (int nc = 0; nc < 2; nc++) {
                    int col = hc * 16 + nc * 8 + nl;
                    unsigned b0h = w1hi[(cc * 8 + q) * WPITCH + col];
                    unsigned b1h = w1hi[(cc * 8 + q + 4) * WPITCH + col];
                    unsigned b0l = w1lo[(cc * 8 + q) * WPITCH + col];
                    unsigned b1l = w1lo[(cc * 8 + q + 4) * WPITCH + col];
                    mma16816(z[0][nc], xah[0][cc], b0h, b1h);
                    mma16816(z[0][nc], xah[0][cc], b0l, b1l);
                    mma16816(z[0][nc], xal[0][cc], b0h, b1h);
                    mma16816(z[1][nc], xah[1][cc], b0h, b1h);
                    mma16816(z[1][nc], xah[1][cc], b0l, b1l);
                    mma16816(z[1][nc], xal[1][cc], b0h, b1h);
                }
            }
            // ReLU + split + repack C->A (layouts match natively)
            unsigned Ah[2][4], Al[2][4];
#pragma unroll
            for (int t = 0; t < 2; t++) {
                split2(fmaxf(z[t][0][0], 0.f), fmaxf(z[t][0][1], 0.f), Ah[t][0], Al[t][0]);
                split2(fmaxf(z[t][0][2], 0.f), fmaxf(z[t][0][3], 0.f), Ah[t][1], Al[t][1]);
                split2(fmaxf(z[t][1][0], 0.f), fmaxf(z[t][1][1], 0.f), Ah[t][2], Al[t][2]);
                split2(fmaxf(z[t][1][2], 0.f), fmaxf(z[t][1][3], 0.f), Ah[t][3], Al[t][3]);
            }
            // GEMM2: B-frags loaded once, used by both tiles
#pragma unroll
            for (int kn = 0; kn < 8; kn++) {
                unsigned b0h = w2hi[(hc * 8 + q) * WPITCH + kn * 8 + nl];
                unsigned b1h = w2hi[(hc * 8 + q + 4) * WPITCH + kn * 8 + nl];
                unsigned b0l = w2lo[(hc * 8 + q) * WPITCH + kn * 8 + nl];
                unsigned b1l = w2lo[(hc * 8 + q + 4) * WPITCH + kn * 8 + nl];
                mma16816(acc[0][kn], Ah[0], b0h, b1h);
                mma16816(acc[0][kn], Ah[0], b0l, b1l);
                mma16816(acc[0][kn], Al[0], b0h, b1h);
                mma16816(acc[1][kn], Ah[1], b0h, b1h);
                mma16816(acc[1][kn], Ah[1], b0l, b1l);
                mma16816(acc[1][kn], Al[1], b0h, b1h);
            }
        }
        __syncthreads();   // buffer (c&1) free for restage at c+1
    }

    // ---- softmax + mask staging (xs reused) ----
#pragma unroll
    for (int t = 0; t < 2; t++) {
        const int prow = warp * 32 + t * 16 + g;
        float mA = -1e30f, mB = -1e30f;
#pragma unroll
        for (int kn = 0; kn < 8; kn++) {
            mA = fmaxf(mA, fmaxf(acc[t][kn][0], acc[t][kn][1]));
            mB = fmaxf(mB, fmaxf(acc[t][kn][2], acc[t][kn][3]));
        }
        mA = fmaxf(mA, __shfl_xor_sync(0xffffffffu, mA, 1));
        mA = fmaxf(mA, __shfl_xor_sync(0xffffffffu, mA, 2));
        mB = fmaxf(mB, __shfl_xor_sync(0xffffffffu, mB, 1));
        mB = fmaxf(mB, __shfl_xor_sync(0xffffffffu, mB, 2));
        float sA = 0.f, sB = 0.f;
#pragma unroll
        for (int kn = 0; kn < 8; kn++) {
            acc[t][kn][0] = __expf(acc[t][kn][0] - mA); sA += acc[t][kn][0];
            acc[t][kn][1] = __expf(acc[t][kn][1] - mA); sA += acc[t][kn][1];
            acc[t][kn][2] = __expf(acc[t][kn][2] - mB); sB += acc[t][kn][2];
            acc[t][kn][3] = __expf(acc[t][kn][3] - mB); sB += acc[t][kn][3];
        }
        sA += __shfl_xor_sync(0xffffffffu, sA, 1);
        sA += __shfl_xor_sync(0xffffffffu, sA, 2);
        sB += __shfl_xor_sync(0xffffffffu, sB, 1);
        sB += __shfl_xor_sync(0xffffffffu, sB, 2);
        const float invA = 1.0f / sA, invB = 1.0f / sB;
#pragma unroll
        for (int kn = 0; kn < 8; kn++) {
            int c0 = kn * 8 + 2 * q;
            xs[c0 * XS_PITCH + prow]           = acc[t][kn][0] * invA;
            xs[(c0 + 1) * XS_PITCH + prow]     = acc[t][kn][1] * invA;
            xs[c0 * XS_PITCH + prow + 8]       = acc[t][kn][2] * invB;
            xs[(c0 + 1) * XS_PITCH + prow + 8] = acc[t][kn][3] * invB;
        }
    }
    __syncthreads();

    // coalesced mask store
    float* gm = g_mask + (size_t)b * KK * HW + p0;
    for (int i = tid; i < KK * TP; i += NT) {
        int k = i >> 7, px = i & 127;
        gm[(size_t)k * HW + px] = xs[k * XS_PITCH + px];
    }
}

// ---------------------------------------------------------------
// K2: per-(b,k) reductions over pixels: sum, max, img-weighted sums
// ---------------------------------------------------------------
__global__ __launch_bounds__(256)
void k_reduce(const float* __restrict__ img)
{
    __shared__ float smr[256];
    const int bk = blockIdx.x;
    const int b = bk >> 6, k = bk & 63;
    const float* gm = g_mask + (size_t)bk * HW;
    const float* im = img + (size_t)b * 3 * HW;

    float s = 0.f, mx = -1e30f, c0 = 0.f, c1 = 0.f, c2 = 0.f;
    for (int p = threadIdx.x; p < HW; p += 256) {
        const float mv = __ldcs(&gm[p]);
        s += mv;
        mx = fmaxf(mx, mv);
        c0 = fmaf(mv, __ldg(&im[p]),          c0);
        c1 = fmaf(mv, __ldg(&im[p + HW]),     c1);
        c2 = fmaf(mv, __ldg(&im[p + 2 * HW]), c2);
    }

    const int t = threadIdx.x;
    float ts, tc0, tc1, tc2, tmx;
    smr[t] = s;  __syncthreads();
    for (int st = 128; st > 0; st >>= 1) { if (t < st) smr[t] += smr[t + st]; __syncthreads(); }
    ts = smr[0]; __syncthreads();
    smr[t] = c0; __syncthreads();
    for (int st = 128; st > 0; st >>= 1) { if (t < st) smr[t] += smr[t + st]; __syncthreads(); }
    tc0 = smr[0]; __syncthreads();
    smr[t] = c1; __syncthreads();
    for (int st = 128; st > 0; st >>= 1) { if (t < st) smr[t] += smr[t + st]; __syncthreads(); }
    tc1 = smr[0]; __syncthreads();
    smr[t] = c2; __syncthreads();
    for (int st = 128; st > 0; st >>= 1) { if (t < st) smr[t] += smr[t + st]; __syncthreads(); }
    tc2 = smr[0]; __syncthreads();
    smr[t] = mx; __syncthreads();
    for (int st = 128; st > 0; st >>= 1) { if (t < st) smr[t] = fmaxf(smr[t], smr[t + st]); __syncthreads(); }
    tmx = smr[0];

    if (t == 0) {
        const float invhw = 1.0f / (float)HW;
        g_bkmean[bk] = ts * invhw;
        g_bkmax[bk]  = tmx;
        g_wc[(b * 3 + 0) * KK + k] = tc0 * invhw;
        g_wc[(b * 3 + 1) * KK + k] = tc1 * invhw;
        g_wc[(b * 3 + 2) * KK + k] = tc2 * invhw;
    }
}

// ---------------------------------------------------------------
// K3: scalar outputs
// ---------------------------------------------------------------
__global__ void k_final(float* __restrict__ out)
{
    __shared__ float smr[512];
    __shared__ float bmean[NB], bstd[NB];
    const int t = threadIdx.x;

    smr[t] = g_bkmax[t]; __syncthreads();
    for (int st = 256; st > 0; st >>= 1) { if (t < st) smr[t] += smr[t + st]; __syncthreads(); }
    if (t == 0) out[(size_t)NB * 3 * HW] = smr[0] * (1.0f / 512.0f);
    __syncthreads();

    const float mv = g_bkmean[t];
    smr[t] = mv; __syncthreads();
    if (t < NB) {
        float sbm = 0.f;
        for (int k = 0; k < KK; k++) sbm += smr[t * KK + k];
        bmean[t] = sbm * (1.0f / KK);
    }
    __syncthreads();
    const float d = mv - bmean[t >> 6];
    smr[t] = d * d; __syncthreads();
    if (t < NB) {
        float sbm = 0.f;
        for (int k = 0; k < KK; k++) sbm += smr[t * KK + k];
        bstd[t] = sqrtf(sbm / (float)(KK - 1));
    }
    __syncthreads();
    if (t == 0) {
        float sbm = 0.f;
        for (int bb = 0; bb < NB; bb++) sbm += bstd[bb];
        out[(size_t)NB * 3 * HW + 1] = sbm * (1.0f / NB);
    }
}

// ---------------------------------------------------------------
// K4: transformed_img[b,c,p] = sum_k mask[b,k,p] * wc[b,c,k]
// ---------------------------------------------------------------
__global__ __launch_bounds__(256)
void k_transform(float* __restrict__ out)
{
    __shared__ float wcs[3 * KK];
    const int b = blockIdx.x >> 8;
    const int p = ((blockIdx.x & 255) << 8) + threadIdx.x;
    if (threadIdx.x < 3 * KK) wcs[threadIdx.x] = g_wc[b * 3 * KK + threadIdx.x];
    __syncthreads();

    const float* gm = g_mask + (size_t)b * KK * HW + p;
    float o0 = 0.f, o1 = 0.f, o2 = 0.f;
#pragma unroll
    for (int k = 0; k < KK; k++) {
        const float mv = __ldcs(&gm[(size_t)k * HW]);
        o0 = fmaf(mv, wcs[k],          o0);
        o1 = fmaf(mv, wcs[KK + k],     o1);
        o2 = fmaf(mv, wcs[2 * KK + k], o2);
    }
    out[((size_t)b * 3 + 0) * HW + p] = o0;
    out[((size_t)b * 3 + 1) * HW + p] = o1;
    out[((size_t)b * 3 + 2) * HW + p] = o2;
}

// ---------------------------------------------------------------
extern "C" void kernel_launch(void* const* d_in, const int* in_sizes, int n_in,
                              void* d_out, int out_size)
{
    const float* img  = (const float*)d_in[0];
    const float* feat = (const float*)d_in[1];
    // d_in[2] = coord_map (unused)
    const float* w1 = (const float*)d_in[3];
    const float* b1 = (const float*)d_in[4];
    const float* w2 = (const float*)d_in[5];
    const float* b2 = (const float*)d_in[6];
    float* out = (float*)d_out;

    cudaFuncSetAttribute(k_mask, cudaFuncAttributeMaxDynamicSharedMemorySize, SMEM_REQ);

    k_prep<<<128, 256>>>(w1, w2);
    k_mask<<<NB * (HW / TP), NT, SMEM_REQ>>>(feat, b1, b2);
    k_reduce<<<NB * KK, 256>>>(img);
    k_final<<<1, 512>>>(out);
    k_transform<<<NB * (HW / 256), 256>>>(out);
}